// round 7
// baseline (speedup 1.0000x reference)
#include <cuda_runtime.h>
#include <math.h>

#define KC       10
#define BT       256
#define NC       1152
#define ICC      8
#define OC       16
#define BTILE    2
#define NTHREADS 576
#define NWARP    18
#define WPB      9          // warps per batch element
#define RPB      288        // threads per batch element
#define RSTRIDE  144        // distinct r per batch element (RPB/2)
#define JROWS    8          // half-rows owned per thread: NC/RSTRIDE

struct SmemLayout {
    float sred[NWARP][OC];            // per-warp s partials, component-indexed
    alignas(16) float v[BTILE][OC];   // v_j  (16B-aligned: read via LDS.128)
    float zred[NWARP];                // per-warp Z partials
};

// Reduce an 8-float vector over the 16 same-oh lanes (xor 2,4,8), then join
// halves (xor 16). 8 SHFLs. Returns the fully reduced component; *Lp = local
// component index 0..7 this lane ends up holding.
__device__ __forceinline__ float reduce8(const float a[8], int lane, int* Lp) {
    const bool s1 = lane & 2, s2 = lane & 4, s3 = lane & 8;
    float t4[4], t2[2], r;
    #pragma unroll
    for (int j = 0; j < 4; j++) {
        const float send = s1 ? a[j]     : a[4 + j];
        const float keep = s1 ? a[4 + j] : a[j];
        t4[j] = keep + __shfl_xor_sync(0xffffffffu, send, 2);
    }
    #pragma unroll
    for (int j = 0; j < 2; j++) {
        const float send = s2 ? t4[j]     : t4[2 + j];
        const float keep = s2 ? t4[2 + j] : t4[j];
        t2[j] = keep + __shfl_xor_sync(0xffffffffu, send, 4);
    }
    {
        const float send = s3 ? t2[0] : t2[1];
        const float keep = s3 ? t2[1] : t2[0];
        r = keep + __shfl_xor_sync(0xffffffffu, send, 8);
    }
    r += __shfl_xor_sync(0xffffffffu, r, 16);
    *Lp = (((lane >> 1) & 1) << 2) | (((lane >> 2) & 1) << 1) | ((lane >> 3) & 1);
    return r;
}

// Write this lane's reduced s component into sred[w][o].
// Thread's component set: {4*oh + (L&3)} for L<4, {8 + 4*oh + (L&3)} for L>=4.
__device__ __forceinline__ void store_comp(SmemLayout* sm, int w, int oh, int L,
                                           int lane, float val) {
    if (lane < 16) {
        const int o = 4 * oh + (L & 3) + ((L & 4) << 1);
        sm->sred[w][o] = val;
    }
}

// 32-thread squash: combine warp partials, normalize, squash, store v (and out).
__device__ __forceinline__ void squash_stage(SmemLayout* sm, int t, bool uniform,
                                             bool writeOut, float* out, int k, int b0) {
    if (t < 32) {
        const int b = t >> 4, o = t & 15;
        float s = 0.f;
        #pragma unroll
        for (int ww = 0; ww < WPB; ww++) s += sm->sred[b * WPB + ww][o];
        float Z;
        if (uniform) {
            Z = (float)NC;
        } else {
            Z = 0.f;
            #pragma unroll
            for (int ww = 0; ww < WPB; ww++) Z += sm->zred[b * WPB + ww];
        }
        s /= Z;
        float sq = s * s;
        #pragma unroll
        for (int sft = 1; sft < 16; sft <<= 1)
            sq += __shfl_xor_sync(0xffffffffu, sq, sft);
        const float v = s * sqrtf(sq) / (1.0f + sq);    // squash
        sm->v[b][o] = v;
        if (writeOut) out[((size_t)k * BT + b0 + b) * OC + o] = v;
    }
    __syncthreads();
}

__global__ __launch_bounds__(NTHREADS, 1)
void caps_routing_kernel(const float* __restrict__ u, const float* __restrict__ W,
                         float* __restrict__ out) {
    __shared__ SmemLayout sm;

    const int k    = blockIdx.y;
    const int b0   = blockIdx.x * BTILE;
    const int t    = threadIdx.x;
    const int lane = t & 31, w = t >> 5;
    const int b    = (t >= RPB) ? 1 : 0;     // warps 0-8 -> b0, warps 9-17 -> b1
    const int tt   = t - b * RPB;
    const int oh   = tt & 1;                 // which interleaved half of the row
    const int r    = tt >> 1;                // 0..143

    // Register-resident u_hat: 8 half-rows x 8 floats = 64 regs.
    // uh0[j] holds comps [4oh, 4oh+4); uh1[j] holds comps [8+4oh, 8+4oh+4).
    float4 uh0[JROWS], uh1[JROWS];

    // ---- Phase 1: u_hat straight into registers; fuse iteration-0 s-sum ----
    {
        const float* Wk = W + (size_t)k * NC * ICC * OC + oh * 4;
        const float* ub = u + (size_t)(b0 + b) * NC * ICC;
        float4 s0a = make_float4(0.f,0.f,0.f,0.f), s0b = make_float4(0.f,0.f,0.f,0.f);
        #pragma unroll
        for (int j = 0; j < JROWS; j++) {
            const int n = r + j * RSTRIDE;
            const float4 ua = *(const float4*)(ub + (size_t)n * ICC);
            const float4 uv = *(const float4*)(ub + (size_t)n * ICC + 4);
            const float uu[8] = {ua.x, ua.y, ua.z, ua.w, uv.x, uv.y, uv.z, uv.w};
            float4 a0 = make_float4(0.f,0.f,0.f,0.f);
            float4 a1 = make_float4(0.f,0.f,0.f,0.f);
            const float* wp = Wk + (size_t)n * ICC * OC;
            #pragma unroll
            for (int i = 0; i < ICC; i++) {
                const float4 w0 = *(const float4*)(wp + i * OC);      // comps 4oh..
                const float4 w1 = *(const float4*)(wp + i * OC + 8);  // comps 8+4oh..
                a0.x = fmaf(w0.x, uu[i], a0.x); a0.y = fmaf(w0.y, uu[i], a0.y);
                a0.z = fmaf(w0.z, uu[i], a0.z); a0.w = fmaf(w0.w, uu[i], a0.w);
                a1.x = fmaf(w1.x, uu[i], a1.x); a1.y = fmaf(w1.y, uu[i], a1.y);
                a1.z = fmaf(w1.z, uu[i], a1.z); a1.w = fmaf(w1.w, uu[i], a1.w);
            }
            uh0[j] = a0; uh1[j] = a1;
            s0a.x += a0.x; s0a.y += a0.y; s0a.z += a0.z; s0a.w += a0.w;
            s0b.x += a1.x; s0b.y += a1.y; s0b.z += a1.z; s0b.w += a1.w;
        }
        const float sa[8] = {s0a.x, s0a.y, s0a.z, s0a.w, s0b.x, s0b.y, s0b.z, s0b.w};
        int L; const float sv = reduce8(sa, lane, &L);
        store_comp(&sm, w, oh, L, lane, sv);
    }
    __syncthreads();

    // ---- Iteration 0: b_ij = 0 => c uniform; s already reduced ----
    squash_stage(&sm, t, /*uniform=*/true, /*writeOut=*/false, out, k, b0);

    float logit[JROWS];

    #pragma unroll 1
    for (int iter = 1; iter < 3; iter++) {
        // Fused a + exp + weighted-s, entirely from registers.
        const float4 v0 = *(const float4*)&sm.v[b][4 * oh];        // 16B-aligned
        const float4 v1 = *(const float4*)&sm.v[b][8 + 4 * oh];
        float4 sc0 = make_float4(0.f,0.f,0.f,0.f), sc1 = make_float4(0.f,0.f,0.f,0.f);
        float z = 0.f;
        #pragma unroll
        for (int j = 0; j < JROWS; j++) {
            const float4 h0 = uh0[j], h1 = uh1[j];
            float p = h0.x * v0.x;
            p = fmaf(h0.y, v0.y, p); p = fmaf(h0.z, v0.z, p); p = fmaf(h0.w, v0.w, p);
            p = fmaf(h1.x, v1.x, p); p = fmaf(h1.y, v1.y, p);
            p = fmaf(h1.z, v1.z, p); p = fmaf(h1.w, v1.w, p);
            p += __shfl_xor_sync(0xffffffffu, p, 1);     // join pair's half-dots
            if (iter == 2) p += logit[j];
            logit[j] = p;
            const float c = __expf(p);    // softmax shift-invariant; |p| << 88
            z += c;
            sc0.x = fmaf(c, h0.x, sc0.x); sc0.y = fmaf(c, h0.y, sc0.y);
            sc0.z = fmaf(c, h0.z, sc0.z); sc0.w = fmaf(c, h0.w, sc0.w);
            sc1.x = fmaf(c, h1.x, sc1.x); sc1.y = fmaf(c, h1.y, sc1.y);
            sc1.z = fmaf(c, h1.z, sc1.z); sc1.w = fmaf(c, h1.w, sc1.w);
        }
        const float sa[8] = {sc0.x, sc0.y, sc0.z, sc0.w, sc1.x, sc1.y, sc1.z, sc1.w};
        int L; const float sv = reduce8(sa, lane, &L);
        // z: pairs (xor 1) hold identical c -> reduce over {2,4,8,16} is exact
        #pragma unroll
        for (int sft = 2; sft <= 16; sft <<= 1)
            z += __shfl_xor_sync(0xffffffffu, z, sft);
        store_comp(&sm, w, oh, L, lane, sv);
        if (lane == 0) sm.zred[w] = z;
        __syncthreads();

        squash_stage(&sm, t, /*uniform=*/false, /*writeOut=*/(iter == 2), out, k, b0);
    }
}

extern "C" void kernel_launch(void* const* d_in, const int* in_sizes, int n_in,
                              void* d_out, int out_size) {
    const float* u = (const float*)d_in[0];   // [256, 1152, 8]
    const float* W = (const float*)d_in[1];   // [10, 1152, 8, 16]
    float* out = (float*)d_out;               // [10, 256, 1, 1, 16]

    dim3 grid(BT / BTILE, KC);                // 128 x 10 = 1280 CTAs
    caps_routing_kernel<<<grid, NTHREADS>>>(u, W, out);
}

// round 10
// speedup vs baseline: 2.3510x; 2.3510x over previous
#include <cuda_runtime.h>
#include <math.h>

#define KC       10
#define BT       256
#define NC       1152
#define ICC      8
#define OC       16
#define BTILE    2
#define NTHREADS 512          // 16 warps -> 4/SMSP -> 128-reg budget (no spills)
#define NWARP    16
#define RSTRIDE  128          // distinct r per CTA
#define JQ       9            // rows per thread: NC / RSTRIDE

struct SmemLayout {
    float sred[NWARP][BTILE][OC];       // per-warp s partials
    float zred[NWARP][BTILE];           // per-warp Z partials
    alignas(16) float vsum[BTILE][OC];  // running sum of v's (b_ij = uh . vsum)
};

// Reduce 8 values over the 8 lanes sharing this oq (lane bits 2,3,4).
// Splitting butterfly: 7 SHFL-adds. Returns fully reduced value; *Lp in [0,8).
__device__ __forceinline__ float reduce8q(const float a[8], int lane, int* Lp) {
    const bool s1 = lane & 4, s2 = lane & 8, s3 = lane & 16;
    float t4[4], t2[2], r;
    #pragma unroll
    for (int j = 0; j < 4; j++) {
        const float send = s1 ? a[j]     : a[4 + j];
        const float keep = s1 ? a[4 + j] : a[j];
        t4[j] = keep + __shfl_xor_sync(0xffffffffu, send, 4);
    }
    #pragma unroll
    for (int j = 0; j < 2; j++) {
        const float send = s2 ? t4[j]     : t4[2 + j];
        const float keep = s2 ? t4[2 + j] : t4[j];
        t2[j] = keep + __shfl_xor_sync(0xffffffffu, send, 8);
    }
    {
        const float send = s3 ? t2[0] : t2[1];
        const float keep = s3 ? t2[1] : t2[0];
        r = keep + __shfl_xor_sync(0xffffffffu, send, 16);
    }
    *Lp = (s1 ? 4 : 0) | (s2 ? 2 : 0) | (s3 ? 1 : 0);
    return r;
}

// Every lane stores its reduced (b, comp) partial: L = 4*b + c, o = 4*oq + c.
__device__ __forceinline__ void store_sred(SmemLayout* sm, int w, int oq, int L, float v) {
    sm->sred[w][L >> 2][4 * oq + (L & 3)] = v;
}

// Reduce z0 (b=0) and z1 (b=1) across the warp. Each (n)'s c is replicated
// over 4 oq-lanes -> divide by 4. Even lane -> Z0, odd lane -> Z1.
__device__ __forceinline__ void store_zred(SmemLayout* sm, int w, int lane,
                                           float z0, float z1) {
    const float send = (lane & 1) ? z0 : z1;
    const float keep = (lane & 1) ? z1 : z0;
    float zz = keep + __shfl_xor_sync(0xffffffffu, send, 1);
    #pragma unroll
    for (int sft = 2; sft <= 16; sft <<= 1)
        zz += __shfl_xor_sync(0xffffffffu, zz, sft);
    if (lane < 2) sm->zred[w][lane] = 0.25f * zz;
}

// 32-thread stage: combine warp partials, normalize, squash, accumulate vsum.
__device__ __forceinline__ void squash_stage(SmemLayout* sm, int t, bool uniform,
                                             bool first, bool writeOut,
                                             float* out, int k, int b0) {
    if (t < 32) {
        const int b = t >> 4, o = t & 15;
        float s = 0.f;
        #pragma unroll
        for (int w = 0; w < NWARP; w++) s += sm->sred[w][b][o];
        float Z;
        if (uniform) {
            Z = (float)NC;
        } else {
            Z = 0.f;
            #pragma unroll
            for (int w = 0; w < NWARP; w++) Z += sm->zred[w][b];
        }
        s /= Z;
        float sq = s * s;
        #pragma unroll
        for (int sft = 1; sft < 16; sft <<= 1)       // 16-lane b-group
            sq += __shfl_xor_sync(0xffffffffu, sq, sft);
        const float v = s * sqrtf(sq) / (1.0f + sq); // squash
        sm->vsum[b][o] = first ? v : (sm->vsum[b][o] + v);
        if (writeOut) out[((size_t)k * BT + b0 + b) * OC + o] = v;
    }
    __syncthreads();
}

__global__ __launch_bounds__(NTHREADS, 1)
void caps_routing_kernel(const float* __restrict__ u, const float* __restrict__ W,
                         float* __restrict__ out) {
    __shared__ SmemLayout sm;

    const int k    = blockIdx.y;
    const int b0   = blockIdx.x * BTILE;
    const int t    = threadIdx.x;
    const int lane = t & 31, w = t >> 5;
    const int oq   = t & 3;              // quarter-row: comps [4oq, 4oq+4)
    const int r    = t >> 2;             // 0..127

    // Register-resident u_hat quarters, BOTH batch elements: 2 x 9 x 4 = 72 regs.
    float4 uh[BTILE][JQ];

    // ---- Phase 1: u_hat into registers (W read ONCE per CTA); fuse iter-0 s-sum ----
    {
        const float* Wk  = W + (size_t)k * NC * ICC * OC + oq * 4;
        const float* ub0 = u + (size_t)b0 * NC * ICC;
        const float* ub1 = ub0 + (size_t)NC * ICC;
        float4 s0 = make_float4(0.f,0.f,0.f,0.f), s1 = make_float4(0.f,0.f,0.f,0.f);
        #pragma unroll
        for (int j = 0; j < JQ; j++) {
            const int n = r + j * RSTRIDE;
            const float4 p0 = *(const float4*)(ub0 + (size_t)n * ICC);
            const float4 p1 = *(const float4*)(ub0 + (size_t)n * ICC + 4);
            const float4 q0 = *(const float4*)(ub1 + (size_t)n * ICC);
            const float4 q1 = *(const float4*)(ub1 + (size_t)n * ICC + 4);
            const float u0[8] = {p0.x, p0.y, p0.z, p0.w, p1.x, p1.y, p1.z, p1.w};
            const float u1[8] = {q0.x, q0.y, q0.z, q0.w, q1.x, q1.y, q1.z, q1.w};
            float4 a0 = make_float4(0.f,0.f,0.f,0.f);
            float4 a1 = make_float4(0.f,0.f,0.f,0.f);
            const float* wp = Wk + (size_t)n * ICC * OC;
            #pragma unroll
            for (int i = 0; i < ICC; i++) {
                const float4 wv = *(const float4*)(wp + i * OC);
                a0.x = fmaf(wv.x, u0[i], a0.x); a0.y = fmaf(wv.y, u0[i], a0.y);
                a0.z = fmaf(wv.z, u0[i], a0.z); a0.w = fmaf(wv.w, u0[i], a0.w);
                a1.x = fmaf(wv.x, u1[i], a1.x); a1.y = fmaf(wv.y, u1[i], a1.y);
                a1.z = fmaf(wv.z, u1[i], a1.z); a1.w = fmaf(wv.w, u1[i], a1.w);
            }
            uh[0][j] = a0; uh[1][j] = a1;
            s0.x += a0.x; s0.y += a0.y; s0.z += a0.z; s0.w += a0.w;
            s1.x += a1.x; s1.y += a1.y; s1.z += a1.z; s1.w += a1.w;
        }
        const float sa[8] = {s0.x, s0.y, s0.z, s0.w, s1.x, s1.y, s1.z, s1.w};
        int L; const float sv = reduce8q(sa, lane, &L);
        store_sred(&sm, w, oq, L, sv);
    }
    __syncthreads();

    // ---- Iteration 0: b_ij = 0 => c uniform; s already reduced ----
    squash_stage(&sm, t, /*uniform=*/true, /*first=*/true, /*writeOut=*/false, out, k, b0);

    // ---- Iterations 1,2: p = uh . vsum (b_ij is linear in uh -> no logit storage) ----
    #pragma unroll 1
    for (int iter = 1; iter < 3; iter++) {
        const float4 v0 = *(const float4*)&sm.vsum[0][4 * oq];   // 16B-aligned
        const float4 v1 = *(const float4*)&sm.vsum[1][4 * oq];
        float4 sc0 = make_float4(0.f,0.f,0.f,0.f), sc1 = make_float4(0.f,0.f,0.f,0.f);
        float z0 = 0.f, z1 = 0.f;
        #pragma unroll
        for (int j = 0; j < JQ; j++) {
            const float4 h0 = uh[0][j], h1 = uh[1][j];
            float pa = h0.x * v0.x;
            pa = fmaf(h0.y, v0.y, pa); pa = fmaf(h0.z, v0.z, pa); pa = fmaf(h0.w, v0.w, pa);
            float pb = h1.x * v1.x;
            pb = fmaf(h1.y, v1.y, pb); pb = fmaf(h1.z, v1.z, pb); pb = fmaf(h1.w, v1.w, pb);
            pa += __shfl_xor_sync(0xffffffffu, pa, 1);   // join 4 quarter-dots
            pb += __shfl_xor_sync(0xffffffffu, pb, 1);
            pa += __shfl_xor_sync(0xffffffffu, pa, 2);
            pb += __shfl_xor_sync(0xffffffffu, pb, 2);
            const float c0 = __expf(pa);   // softmax shift-invariant; |p| <~ 30
            const float c1 = __expf(pb);
            z0 += c0; z1 += c1;
            sc0.x = fmaf(c0, h0.x, sc0.x); sc0.y = fmaf(c0, h0.y, sc0.y);
            sc0.z = fmaf(c0, h0.z, sc0.z); sc0.w = fmaf(c0, h0.w, sc0.w);
            sc1.x = fmaf(c1, h1.x, sc1.x); sc1.y = fmaf(c1, h1.y, sc1.y);
            sc1.z = fmaf(c1, h1.z, sc1.z); sc1.w = fmaf(c1, h1.w, sc1.w);
        }
        const float sa[8] = {sc0.x, sc0.y, sc0.z, sc0.w, sc1.x, sc1.y, sc1.z, sc1.w};
        int L; const float sv = reduce8q(sa, lane, &L);
        store_sred(&sm, w, oq, L, sv);
        store_zred(&sm, w, lane, z0, z1);
        __syncthreads();

        squash_stage(&sm, t, /*uniform=*/false, /*first=*/false,
                     /*writeOut=*/(iter == 2), out, k, b0);
    }
}

extern "C" void kernel_launch(void* const* d_in, const int* in_sizes, int n_in,
                              void* d_out, int out_size) {
    const float* u = (const float*)d_in[0];   // [256, 1152, 8]
    const float* W = (const float*)d_in[1];   // [10, 1152, 8, 16]
    float* out = (float*)d_out;               // [10, 256, 1, 1, 16]

    dim3 grid(BT / BTILE, KC);                // 128 x 10 = 1280 CTAs
    caps_routing_kernel<<<grid, NTHREADS>>>(u, W, out);
}